// round 8
// baseline (speedup 1.0000x reference)
#include <cuda_runtime.h>

#define N 8192
#define D 64

// ---- scratch (no cudaMalloc allowed; __device__ globals are the sanctioned path) ----
__device__ float g_K [(size_t)N * N];   // 256 MB: K_ij  = exp(-C_ij/eps)
__device__ float g_KC[(size_t)N * N];   // 256 MB: K_ij * C_ij
__device__ float g_sp[N];
__device__ float g_sq[N];
__device__ float g_u [N];
__device__ float g_v [N];
__device__ float g_part[N];

__device__ __forceinline__ float fsqrt_approx(float x) {
    float r; asm("sqrt.approx.f32 %0, %1;" : "=f"(r) : "f"(x)); return r;
}
__device__ __forceinline__ float fex2_approx(float x) {
    float r; asm("ex2.approx.f32 %0, %1;" : "=f"(r) : "f"(x)); return r;
}

// -(1/eps) * log2(e),  eps = 0.1
#define NEG_INVEPS_LOG2E (-14.4269504088896340736f)

// ---------------------------------------------------------------------------
// 1) row norms of P and Q; also (re)initialize u = 1/D  (deterministic per call)
// ---------------------------------------------------------------------------
__global__ void norms_kernel(const float* __restrict__ P, const float* __restrict__ Q) {
    int row  = blockIdx.x * blockDim.y + threadIdx.y;   // one warp per row
    int lane = threadIdx.x;
    const float* p = P + (size_t)row * D;
    const float* q = Q + (size_t)row * D;
    float s = p[lane] * p[lane] + p[lane + 32] * p[lane + 32];
    float t = q[lane] * q[lane] + q[lane + 32] * q[lane + 32];
    #pragma unroll
    for (int o = 16; o; o >>= 1) {
        s += __shfl_xor_sync(0xffffffffu, s, o);
        t += __shfl_xor_sync(0xffffffffu, t, o);
    }
    if (lane == 0) { g_sp[row] = s; g_sq[row] = t; }
    if (lane == 1) { g_u[row] = 1.0f / (float)D; }
}

// ---------------------------------------------------------------------------
// 2) build K and K*C: 64x64 output tile per block, full K-dim (D=64) in smem
// ---------------------------------------------------------------------------
__global__ __launch_bounds__(256) void build_kernel(const float* __restrict__ P,
                                                    const float* __restrict__ Q) {
    __shared__ float As[D][65];   // As[k][row]  (padded: conflict-free)
    __shared__ float Bs[D][65];   // Bs[k][col]

    const int r0  = blockIdx.y * 64;
    const int c0  = blockIdx.x * 64;
    const int tid = threadIdx.x;

    // cooperative load: 64 rows x 64 k, float4 along k (coalesced), transpose into smem
    #pragma unroll
    for (int it = 0; it < 4; it++) {
        int idx = tid + it * 256;           // 0..1023
        int r   = idx >> 4;                 // 0..63
        int kq  = (idx & 15) << 2;          // 0,4,...,60
        float4 a = *(const float4*)(P + (size_t)(r0 + r) * D + kq);
        As[kq + 0][r] = a.x; As[kq + 1][r] = a.y; As[kq + 2][r] = a.z; As[kq + 3][r] = a.w;
        float4 b = *(const float4*)(Q + (size_t)(c0 + r) * D + kq);
        Bs[kq + 0][r] = b.x; Bs[kq + 1][r] = b.y; Bs[kq + 2][r] = b.z; Bs[kq + 3][r] = b.w;
    }
    __syncthreads();

    const int tr = (tid >> 4) << 2;   // 0..60
    const int tc = (tid & 15) << 2;   // 0..60

    float acc[4][4] = {};
    #pragma unroll 16
    for (int k = 0; k < D; k++) {
        float a0 = As[k][tr + 0], a1 = As[k][tr + 1], a2 = As[k][tr + 2], a3 = As[k][tr + 3];
        float b0 = Bs[k][tc + 0], b1 = Bs[k][tc + 1], b2 = Bs[k][tc + 2], b3 = Bs[k][tc + 3];
        acc[0][0] += a0 * b0; acc[0][1] += a0 * b1; acc[0][2] += a0 * b2; acc[0][3] += a0 * b3;
        acc[1][0] += a1 * b0; acc[1][1] += a1 * b1; acc[1][2] += a1 * b2; acc[1][3] += a1 * b3;
        acc[2][0] += a2 * b0; acc[2][1] += a2 * b1; acc[2][2] += a2 * b2; acc[2][3] += a2 * b3;
        acc[3][0] += a3 * b0; acc[3][1] += a3 * b1; acc[3][2] += a3 * b2; acc[3][3] += a3 * b3;
    }

    float spv[4], sqv[4];
    #pragma unroll
    for (int i = 0; i < 4; i++) { spv[i] = g_sp[r0 + tr + i]; sqv[i] = g_sq[c0 + tc + i]; }

    #pragma unroll
    for (int i = 0; i < 4; i++) {
        float kv[4], kcv[4];
        #pragma unroll
        for (int j = 0; j < 4; j++) {
            float s = fmaxf(spv[i] + sqv[j] - 2.0f * acc[i][j], 0.0f);
            float c = fsqrt_approx(s);                 // C_ij
            float e = fex2_approx(c * NEG_INVEPS_LOG2E); // K_ij
            kv[j]  = e;
            kcv[j] = e * c;
        }
        size_t off = (size_t)(r0 + tr + i) * N + (size_t)(c0 + tc);
        *(float4*)(g_K  + off) = make_float4(kv[0],  kv[1],  kv[2],  kv[3]);
        *(float4*)(g_KC + off) = make_float4(kcv[0], kcv[1], kcv[2], kcv[3]);
    }
}

// ---------------------------------------------------------------------------
// 3) Sinkhorn matvec: y_i = 1 / sum_j K_ij x_j     (dir=0: u->v, dir=1: v->u)
// ---------------------------------------------------------------------------
__global__ __launch_bounds__(256) void matvec_kernel(int dir) {
    const float* __restrict__ x = dir ? g_v : g_u;
    float*       __restrict__ y = dir ? g_u : g_v;

    const int row = blockIdx.x;
    const float* kr = g_K + (size_t)row * N;

    float s = 0.0f;
    #pragma unroll
    for (int it = 0; it < 8; it++) {
        int j = (threadIdx.x << 2) + it * 1024;
        float4 kv = *(const float4*)(kr + j);
        float4 xv = *(const float4*)(x  + j);
        s = fmaf(kv.x, xv.x, s); s = fmaf(kv.y, xv.y, s);
        s = fmaf(kv.z, xv.z, s); s = fmaf(kv.w, xv.w, s);
    }
    #pragma unroll
    for (int o = 16; o; o >>= 1) s += __shfl_xor_sync(0xffffffffu, s, o);

    __shared__ float red[8];
    if ((threadIdx.x & 31) == 0) red[threadIdx.x >> 5] = s;
    __syncthreads();
    if (threadIdx.x == 0) {
        float t = 0.0f;
        #pragma unroll
        for (int w = 0; w < 8; w++) t += red[w];
        y[row] = 1.0f / t;
    }
}

// ---------------------------------------------------------------------------
// 4) final: part_i = u_i * sum_j (K*C)_ij v_j
// ---------------------------------------------------------------------------
__global__ __launch_bounds__(256) void final_row_kernel() {
    const int row = blockIdx.x;
    const float* kr = g_KC + (size_t)row * N;

    float s = 0.0f;
    #pragma unroll
    for (int it = 0; it < 8; it++) {
        int j = (threadIdx.x << 2) + it * 1024;
        float4 kv = *(const float4*)(kr + j);
        float4 xv = *(const float4*)(g_v + j);
        s = fmaf(kv.x, xv.x, s); s = fmaf(kv.y, xv.y, s);
        s = fmaf(kv.z, xv.z, s); s = fmaf(kv.w, xv.w, s);
    }
    #pragma unroll
    for (int o = 16; o; o >>= 1) s += __shfl_xor_sync(0xffffffffu, s, o);

    __shared__ float red[8];
    if ((threadIdx.x & 31) == 0) red[threadIdx.x >> 5] = s;
    __syncthreads();
    if (threadIdx.x == 0) {
        float t = 0.0f;
        #pragma unroll
        for (int w = 0; w < 8; w++) t += red[w];
        g_part[row] = g_u[row] * t;
    }
}

// 5) deterministic scalar reduce (double accumulation, fixed tree order)
__global__ void reduce_kernel(float* __restrict__ out) {
    __shared__ double sh[256];
    double s = 0.0;
    for (int i = threadIdx.x; i < N; i += 256) s += (double)g_part[i];
    sh[threadIdx.x] = s;
    __syncthreads();
    for (int o = 128; o; o >>= 1) {
        if (threadIdx.x < o) sh[threadIdx.x] += sh[threadIdx.x + o];
        __syncthreads();
    }
    if (threadIdx.x == 0) out[0] = (float)sh[0];
}

// ---------------------------------------------------------------------------
extern "C" void kernel_launch(void* const* d_in, const int* in_sizes, int n_in,
                              void* d_out, int out_size) {
    const float* P = (const float*)d_in[0];
    const float* Q = (const float*)d_in[1];
    float* out = (float*)d_out;

    // norms + u init (one warp per row)
    norms_kernel<<<N / 8, dim3(32, 8)>>>(P, Q);

    // build K and K*C
    dim3 grid(N / 64, N / 64);
    build_kernel<<<grid, 256>>>(P, Q);

    // 5 Sinkhorn iterations: v = 1/(K u); u = 1/(K v)
    for (int it = 0; it < 5; it++) {
        matvec_kernel<<<N, 256>>>(0);   // u -> v
        matvec_kernel<<<N, 256>>>(1);   // v -> u
    }

    // loss = sum_i u_i * sum_j (K*C)_ij v_j
    final_row_kernel<<<N, 256>>>();
    reduce_kernel<<<1, 256>>>(out);
}

// round 11
// speedup vs baseline: 2.2559x; 2.2559x over previous
#include <cuda_runtime.h>
#include <cuda_bf16.h>
#include <cstdint>

#define N 8192
#define D 64

// ---- scratch (__device__ globals: the sanctioned no-alloc path) ----
__device__ __nv_bfloat16 g_K[(size_t)N * N];   // 128 MB: K_ij = exp(-C_ij/eps), bf16
__device__ float g_sp[N];
__device__ float g_sq[N];
__device__ float g_u [N];
__device__ float g_v [N];
__device__ float g_part[N];

__device__ __forceinline__ float fsqrt_approx(float x) {
    float r; asm("sqrt.approx.f32 %0, %1;" : "=f"(r) : "f"(x)); return r;
}
__device__ __forceinline__ float fex2_approx(float x) {
    float r; asm("ex2.approx.f32 %0, %1;" : "=f"(r) : "f"(x)); return r;
}
__device__ __forceinline__ float flg2_approx(float x) {
    float r; asm("lg2.approx.f32 %0, %1;" : "=f"(r) : "f"(x)); return r;
}

// -(1/eps) * log2(e),  eps = 0.1
#define NEG_INVEPS_LOG2E (-14.4269504088896340736f)
// -eps * ln(2)  : C = -eps*ln(K) = lg2(K) * (-eps*ln2)
#define NEG_EPS_LN2      (-0.069314718055994530942f)

// ---------------------------------------------------------------------------
// 1) row norms of P and Q; init u = 1/D  (deterministic per call)
// ---------------------------------------------------------------------------
__global__ void norms_kernel(const float* __restrict__ P, const float* __restrict__ Q) {
    int row  = blockIdx.x * blockDim.y + threadIdx.y;
    int lane = threadIdx.x;
    const float* p = P + (size_t)row * D;
    const float* q = Q + (size_t)row * D;
    float s = p[lane] * p[lane] + p[lane + 32] * p[lane + 32];
    float t = q[lane] * q[lane] + q[lane + 32] * q[lane + 32];
    #pragma unroll
    for (int o = 16; o; o >>= 1) {
        s += __shfl_xor_sync(0xffffffffu, s, o);
        t += __shfl_xor_sync(0xffffffffu, t, o);
    }
    if (lane == 0) { g_sp[row] = s; g_sq[row] = t; }
    if (lane == 1) { g_u[row] = 1.0f / (float)D; }
}

// ---------------------------------------------------------------------------
// 2) build K (bf16) via HMMA mma.sync: 128x128 tile/CTA, 8 warps x (64x32)
//    A = P rows (row-major MxK), B = Q rows (col-major KxN since Q is [n][k])
// ---------------------------------------------------------------------------
#define AS_STRIDE 72    // bf16 elements per smem row (144 B -> bank = 4g+t, conflict-free)
#define CS_STRIDE 136   // bf16 elements per staged output row (272 B -> conflict-free)

__global__ __launch_bounds__(256) void build_kernel(const float* __restrict__ P,
                                                    const float* __restrict__ Q) {
    __shared__ __align__(16) char sm_raw[2 * 128 * AS_STRIDE * 2];   // 36864 B
    __nv_bfloat16* As = (__nv_bfloat16*)sm_raw;                      // [128][72]
    __nv_bfloat16* Bs = (__nv_bfloat16*)(sm_raw + 128 * AS_STRIDE * 2);
    __nv_bfloat16* Cs = (__nv_bfloat16*)sm_raw;                      // reused: [128][136]

    const int tid  = threadIdx.x;
    const int wid  = tid >> 5;
    const int lane = tid & 31;
    const int r0 = blockIdx.y * 128;
    const int c0 = blockIdx.x * 128;

    // cooperative load + fp32->bf16 convert (coalesced float4 per thread)
    #pragma unroll
    for (int it = 0; it < 8; it++) {
        int idx = tid + it * 256;          // 0..2047
        int r   = idx >> 4;                // 0..127
        int k4  = (idx & 15) << 2;         // 0,4,...,60
        float4 a = *(const float4*)(P + (size_t)(r0 + r) * D + k4);
        float4 b = *(const float4*)(Q + (size_t)(c0 + r) * D + k4);
        __nv_bfloat162 a01 = __floats2bfloat162_rn(a.x, a.y);
        __nv_bfloat162 a23 = __floats2bfloat162_rn(a.z, a.w);
        __nv_bfloat162 b01 = __floats2bfloat162_rn(b.x, b.y);
        __nv_bfloat162 b23 = __floats2bfloat162_rn(b.z, b.w);
        uint2 av, bv;
        av.x = *(uint32_t*)&a01; av.y = *(uint32_t*)&a23;
        bv.x = *(uint32_t*)&b01; bv.y = *(uint32_t*)&b23;
        *(uint2*)(As + r * AS_STRIDE + k4) = av;
        *(uint2*)(Bs + r * AS_STRIDE + k4) = bv;
    }
    __syncthreads();

    const int g = lane >> 2;      // 0..7
    const int t = lane & 3;       // 0..3
    const int wr0 = (wid >> 2) * 64;   // warp row offset in tile
    const int wc0 = (wid & 3) * 32;    // warp col offset in tile

    // acc[mi][ni][reg]: m16n8 fp32 fragments; c0=(g,2t) c1=(g,2t+1) c2=(g+8,2t) c3=(g+8,2t+1)
    float acc[4][4][4];
    #pragma unroll
    for (int mi = 0; mi < 4; mi++)
        #pragma unroll
        for (int ni = 0; ni < 4; ni++)
            acc[mi][ni][0] = acc[mi][ni][1] = acc[mi][ni][2] = acc[mi][ni][3] = 0.0f;

    #pragma unroll
    for (int ks = 0; ks < 4; ks++) {
        const int kc = ks * 16 + 2 * t;
        uint32_t af[4][4];
        #pragma unroll
        for (int mi = 0; mi < 4; mi++) {
            const __nv_bfloat16* ar = As + (wr0 + mi * 16 + g) * AS_STRIDE + kc;
            af[mi][0] = *(const uint32_t*)(ar);
            af[mi][1] = *(const uint32_t*)(ar + 8 * AS_STRIDE);
            af[mi][2] = *(const uint32_t*)(ar + 8);
            af[mi][3] = *(const uint32_t*)(ar + 8 * AS_STRIDE + 8);
        }
        uint32_t bf[4][2];
        #pragma unroll
        for (int ni = 0; ni < 4; ni++) {
            const __nv_bfloat16* br = Bs + (wc0 + ni * 8 + g) * AS_STRIDE + kc;
            bf[ni][0] = *(const uint32_t*)(br);
            bf[ni][1] = *(const uint32_t*)(br + 8);
        }
        #pragma unroll
        for (int mi = 0; mi < 4; mi++)
            #pragma unroll
            for (int ni = 0; ni < 4; ni++) {
                asm volatile(
                    "mma.sync.aligned.m16n8k16.row.col.f32.bf16.bf16.f32 "
                    "{%0,%1,%2,%3}, {%4,%5,%6,%7}, {%8,%9}, {%0,%1,%2,%3};"
                    : "+f"(acc[mi][ni][0]), "+f"(acc[mi][ni][1]),
                      "+f"(acc[mi][ni][2]), "+f"(acc[mi][ni][3])
                    : "r"(af[mi][0]), "r"(af[mi][1]), "r"(af[mi][2]), "r"(af[mi][3]),
                      "r"(bf[ni][0]), "r"(bf[ni][1]));
            }
    }
    __syncthreads();   // done reading As/Bs; smem is reused as Cs

    // epilogue: s = max(sp+sq-2*dot, 0); C = sqrt(s); K = ex2(C * -log2e/eps)
    float sp0[4], sp8[4];
    #pragma unroll
    for (int mi = 0; mi < 4; mi++) {
        sp0[mi] = g_sp[r0 + wr0 + mi * 16 + g];
        sp8[mi] = g_sp[r0 + wr0 + mi * 16 + g + 8];
    }
    float sq0[4], sq1[4];
    #pragma unroll
    for (int ni = 0; ni < 4; ni++) {
        sq0[ni] = g_sq[c0 + wc0 + ni * 8 + 2 * t];
        sq1[ni] = g_sq[c0 + wc0 + ni * 8 + 2 * t + 1];
    }

    #pragma unroll
    for (int mi = 0; mi < 4; mi++) {
        #pragma unroll
        for (int ni = 0; ni < 4; ni++) {
            float s00 = fmaxf(sp0[mi] + sq0[ni] - 2.0f * acc[mi][ni][0], 0.0f);
            float s01 = fmaxf(sp0[mi] + sq1[ni] - 2.0f * acc[mi][ni][1], 0.0f);
            float s10 = fmaxf(sp8[mi] + sq0[ni] - 2.0f * acc[mi][ni][2], 0.0f);
            float s11 = fmaxf(sp8[mi] + sq1[ni] - 2.0f * acc[mi][ni][3], 0.0f);
            float k00 = fex2_approx(fsqrt_approx(s00) * NEG_INVEPS_LOG2E);
            float k01 = fex2_approx(fsqrt_approx(s01) * NEG_INVEPS_LOG2E);
            float k10 = fex2_approx(fsqrt_approx(s10) * NEG_INVEPS_LOG2E);
            float k11 = fex2_approx(fsqrt_approx(s11) * NEG_INVEPS_LOG2E);
            __nv_bfloat162 h0 = __floats2bfloat162_rn(k00, k01);
            __nv_bfloat162 h1 = __floats2bfloat162_rn(k10, k11);
            int col = wc0 + ni * 8 + 2 * t;
            *(uint32_t*)(Cs + (wr0 + mi * 16 + g    ) * CS_STRIDE + col) = *(uint32_t*)&h0;
            *(uint32_t*)(Cs + (wr0 + mi * 16 + g + 8) * CS_STRIDE + col) = *(uint32_t*)&h1;
        }
    }
    __syncthreads();

    // coalesced bf16 store: 128 rows x 256 B, uint4 per thread
    #pragma unroll
    for (int it = 0; it < 8; it++) {
        int idx = tid + it * 256;          // 0..2047
        int r   = idx >> 4;                // 0..127
        int cc  = (idx & 15) * 8;          // 0..120
        uint4 v = *(const uint4*)(Cs + r * CS_STRIDE + cc);
        *(uint4*)(g_K + (size_t)(r0 + r) * N + (c0 + cc)) = v;
    }
}

// ---------------------------------------------------------------------------
// 3) Sinkhorn matvec: y_i = 1 / sum_j K_ij x_j   (dir=0: u->v, dir=1: v->u)
// ---------------------------------------------------------------------------
__global__ __launch_bounds__(256) void matvec_kernel(int dir) {
    const float* __restrict__ x = dir ? g_v : g_u;
    float*       __restrict__ y = dir ? g_u : g_v;

    const int row = blockIdx.x;
    const __nv_bfloat16* kr = g_K + (size_t)row * N;

    float s = 0.0f;
    #pragma unroll
    for (int it = 0; it < 4; it++) {
        int j = threadIdx.x * 8 + it * 2048;
        uint4 kw = *(const uint4*)(kr + j);
        float4 x0 = *(const float4*)(x + j);
        float4 x1 = *(const float4*)(x + j + 4);
        float2 k0 = __bfloat1622float2(*(__nv_bfloat162*)&kw.x);
        float2 k1 = __bfloat1622float2(*(__nv_bfloat162*)&kw.y);
        float2 k2 = __bfloat1622float2(*(__nv_bfloat162*)&kw.z);
        float2 k3 = __bfloat1622float2(*(__nv_bfloat162*)&kw.w);
        s = fmaf(k0.x, x0.x, s); s = fmaf(k0.y, x0.y, s);
        s = fmaf(k1.x, x0.z, s); s = fmaf(k1.y, x0.w, s);
        s = fmaf(k2.x, x1.x, s); s = fmaf(k2.y, x1.y, s);
        s = fmaf(k3.x, x1.z, s); s = fmaf(k3.y, x1.w, s);
    }
    #pragma unroll
    for (int o = 16; o; o >>= 1) s += __shfl_xor_sync(0xffffffffu, s, o);

    __shared__ float red[8];
    if ((threadIdx.x & 31) == 0) red[threadIdx.x >> 5] = s;
    __syncthreads();
    if (threadIdx.x == 0) {
        float t = 0.0f;
        #pragma unroll
        for (int w = 0; w < 8; w++) t += red[w];
        y[row] = 1.0f / t;
    }
}

// ---------------------------------------------------------------------------
// 4) final: part_i = u_i * sum_j K_ij * C_ij * v_j, with C = lg2(K) * (-eps*ln2)
// ---------------------------------------------------------------------------
__global__ __launch_bounds__(256) void final_row_kernel() {
    const int row = blockIdx.x;
    const __nv_bfloat16* kr = g_K + (size_t)row * N;

    float s = 0.0f;
    #pragma unroll
    for (int it = 0; it < 4; it++) {
        int j = threadIdx.x * 8 + it * 2048;
        uint4 kw = *(const uint4*)(kr + j);
        float4 v0 = *(const float4*)(g_v + j);
        float4 v1 = *(const float4*)(g_v + j + 4);
        float2 k0 = __bfloat1622float2(*(__nv_bfloat162*)&kw.x);
        float2 k1 = __bfloat1622float2(*(__nv_bfloat162*)&kw.y);
        float2 k2 = __bfloat1622float2(*(__nv_bfloat162*)&kw.z);
        float2 k3 = __bfloat1622float2(*(__nv_bfloat162*)&kw.w);
        float kc;
        kc = k0.x * flg2_approx(k0.x) * NEG_EPS_LN2; s = fmaf(kc, v0.x, s);
        kc = k0.y * flg2_approx(k0.y) * NEG_EPS_LN2; s = fmaf(kc, v0.y, s);
        kc = k1.x * flg2_approx(k1.x) * NEG_EPS_LN2; s = fmaf(kc, v0.z, s);
        kc = k1.y * flg2_approx(k1.y) * NEG_EPS_LN2; s = fmaf(kc, v0.w, s);
        kc = k2.x * flg2_approx(k2.x) * NEG_EPS_LN2; s = fmaf(kc, v1.x, s);
        kc = k2.y * flg2_approx(k2.y) * NEG_EPS_LN2; s = fmaf(kc, v1.y, s);
        kc = k3.x * flg2_approx(k3.x) * NEG_EPS_LN2; s = fmaf(kc, v1.z, s);
        kc = k3.y * flg2_approx(k3.y) * NEG_EPS_LN2; s = fmaf(kc, v1.w, s);
    }
    #pragma unroll
    for (int o = 16; o; o >>= 1) s += __shfl_xor_sync(0xffffffffu, s, o);

    __shared__ float red[8];
    if ((threadIdx.x & 31) == 0) red[threadIdx.x >> 5] = s;
    __syncthreads();
    if (threadIdx.x == 0) {
        float t = 0.0f;
        #pragma unroll
        for (int w = 0; w < 8; w++) t += red[w];
        g_part[row] = g_u[row] * t;
    }
}

// 5) deterministic scalar reduce (double accumulation, fixed tree order)
__global__ void reduce_kernel(float* __restrict__ out) {
    __shared__ double sh[256];
    double s = 0.0;
    for (int i = threadIdx.x; i < N; i += 256) s += (double)g_part[i];
    sh[threadIdx.x] = s;
    __syncthreads();
    for (int o = 128; o; o >>= 1) {
        if (threadIdx.x < o) sh[threadIdx.x] += sh[threadIdx.x + o];
        __syncthreads();
    }
    if (threadIdx.x == 0) out[0] = (float)sh[0];
}

// ---------------------------------------------------------------------------
extern "C" void kernel_launch(void* const* d_in, const int* in_sizes, int n_in,
                              void* d_out, int out_size) {
    const float* P = (const float*)d_in[0];
    const float* Q = (const float*)d_in[1];
    float* out = (float*)d_out;

    norms_kernel<<<N / 8, dim3(32, 8)>>>(P, Q);

    dim3 grid(N / 128, N / 128);
    build_kernel<<<grid, 256>>>(P, Q);

    for (int it = 0; it < 5; it++) {
        matvec_kernel<<<N, 256>>>(0);   // u -> v
        matvec_kernel<<<N, 256>>>(1);   // v -> u
    }

    final_row_kernel<<<N, 256>>>();
    reduce_kernel<<<1, 256>>>(out);
}